// round 2
// baseline (speedup 1.0000x reference)
#include <cuda_runtime.h>
#include <cstdint>
#include <cstdio>

// Problem sizes (fixed by reference_code)
#define NN0 500000
#define NN1 100000
#define NN2 25000
#define EE0 1600000
#define EE1 400000
#define DIN 128
#define DH  256
#define DOUT 128

// ---------------- device scratch (no allocations allowed) ----------------
__device__ float4 g_agg0[(size_t)NN1 * DIN / 4];   // 51.2 MB
__device__ float4 g_cnt0[NN1 / 4];                 // 0.4 MB
__device__ float4 g_h   [(size_t)NN1 * DH / 4];    // 102.4 MB
__device__ float4 g_agg1[(size_t)NN2 * DH / 4];    // 25.6 MB
__device__ float4 g_cnt1[NN2 / 4];                 // 0.1 MB

// ---------------- zero scratch ----------------
#define Z_AGG0 ((size_t)NN1 * DIN / 4)   // 3,200,000
#define Z_AGG1 ((size_t)NN2 * DH  / 4)   // 1,600,000
#define Z_CNT0 ((size_t)NN1 / 4)         // 25,000
#define Z_CNT1 ((size_t)NN2 / 4)         // 6,250
#define Z_TOTAL (Z_AGG0 + Z_AGG1 + Z_CNT0 + Z_CNT1)

__global__ void zero_scratch_kernel() {
    size_t i = (size_t)blockIdx.x * blockDim.x + threadIdx.x;
    if (i >= Z_TOTAL) return;
    const float4 z = make_float4(0.f, 0.f, 0.f, 0.f);
    if (i < Z_AGG0) { g_agg0[i] = z; return; }
    i -= Z_AGG0;
    if (i < Z_AGG1) { g_agg1[i] = z; return; }
    i -= Z_AGG1;
    if (i < Z_CNT0) { g_cnt0[i] = z; return; }
    i -= Z_CNT0;
    g_cnt1[i] = z;
}

// ---------------- edge scatter (atomic mean accumulation) ----------------
__device__ __forceinline__ void red_add_f4(float4* p, float4 v) {
    asm volatile("red.global.add.v4.f32 [%0], {%1,%2,%3,%4};"
                 :: "l"(p), "f"(v.x), "f"(v.y), "f"(v.z), "f"(v.w)
                 : "memory");
}

// one warp per edge, 128 floats = 32 float4 lanes
__global__ void scatter0_kernel(const float4* __restrict__ x4,
                                const int* __restrict__ es,
                                const int* __restrict__ ed) {
    unsigned gtid = blockIdx.x * 256u + threadIdx.x;
    unsigned e = gtid >> 5;
    int lane = gtid & 31;
    int src = es[e];
    int dst = ed[e];
    float4 v = __ldg(&x4[(size_t)src * 32 + lane]);
    red_add_f4(&g_agg0[(size_t)dst * 32 + lane], v);
    if (lane == 0) atomicAdd((float*)g_cnt0 + dst, 1.0f);
}

// 64 threads per edge, 256 floats = 64 float4 lanes, reads g_h
__global__ void scatter1_kernel(const int* __restrict__ es,
                                const int* __restrict__ ed) {
    unsigned gtid = blockIdx.x * 256u + threadIdx.x;
    unsigned e = gtid >> 6;
    int lane = gtid & 63;
    int src = es[e];
    int dst = ed[e];
    float4 v = g_h[(size_t)src * 64 + lane];
    red_add_f4(&g_agg1[(size_t)dst * 64 + lane], v);
    if (lane == 0) atomicAdd((float*)g_cnt1 + dst, 1.0f);
}

// ---------------- packed f32x2 helpers (sm_103a FFMA2 path) ----------------
typedef unsigned long long u64;

__device__ __forceinline__ u64 splat2(float v) {
    u64 r;
    asm("mov.b64 %0, {%1, %1};" : "=l"(r) : "f"(v));
    return r;
}
__device__ __forceinline__ void ffma2(u64& d, u64 a, u64 b) {
    asm("fma.rn.f32x2 %0, %1, %2, %0;" : "+l"(d) : "l"(a), "l"(b));
}
__device__ __forceinline__ float2 unpack2(u64 v) {
    float2 f;
    asm("mov.b64 {%0, %1}, %2;" : "=f"(f.x), "=f"(f.y) : "l"(v));
    return f;
}

// ---------------- fused SAGEConv GEMM (FFMA2, 128x128 tile) ----------------
// out[m,n] = act( sum_k (A0[m,k]/max(cnt[m],1)) * B0[n,k]
//               + sum_k  A1[m,k]                * B1[n,k] + bias[n] )
// A0,A1: [M, D] row-major.  B0,B1: [N, D] row-major.  out: [M, N].
// 256 threads, block tile 128x128, TK=16, per-thread 8 rows x 8 cols
// (cols packed as 4 f32x2 pairs: col = tx*2 + 32*j2 {+0,+1}).
template<int D>
__global__ __launch_bounds__(256, 2)
void sage_gemm2_kernel(const float* __restrict__ A0, const float* __restrict__ cnt,
                       const float* __restrict__ A1,
                       const float* __restrict__ B0, const float* __restrict__ B1,
                       const float* __restrict__ bias,
                       float* __restrict__ out,
                       int M, int N, int do_relu) {
    constexpr int TM = 128, TN = 128, TK = 16;
    __shared__ float As[TK][TM + 2];
    __shared__ float Bs[TK][TN + 2];

    const int tid = threadIdx.x;
    const int tx = tid & 15;          // 16 column-groups (pairs)
    const int ty = tid >> 4;          // 16 row-groups of 8
    const int row0 = blockIdx.x * TM;
    const int col0 = blockIdx.y * TN;

    u64 acc[8][4];
#pragma unroll
    for (int i = 0; i < 8; ++i)
#pragma unroll
        for (int j = 0; j < 4; ++j) acc[i][j] = 0ull;

#pragma unroll 1
    for (int half = 0; half < 2; ++half) {
        const float* __restrict__ A = half ? A1 : A0;
        const float* __restrict__ B = half ? B1 : B0;
#pragma unroll 1
        for (int kb = 0; kb < D; kb += TK) {
            // --- load A tile: 128x16 floats = 512 float4, 2 per thread ---
#pragma unroll
            for (int it = 0; it < 2; ++it) {
                int i = tid + it * 256;
                int m  = i >> 2;
                int k4 = (i & 3) * 4;
                int row = row0 + m;
                float4 v = make_float4(0.f, 0.f, 0.f, 0.f);
                float s = 1.0f;
                if (row < M) {
                    v = *(const float4*)(A + (size_t)row * D + kb + k4);
                    if (half == 0) s = 1.0f / fmaxf(__ldg(cnt + row), 1.0f);
                }
                As[k4 + 0][m] = v.x * s;
                As[k4 + 1][m] = v.y * s;
                As[k4 + 2][m] = v.z * s;
                As[k4 + 3][m] = v.w * s;
            }
            // --- load B tile: 128x16 floats = 512 float4, 2 per thread ---
            // (col0+n < N always: grid.y covers N exactly, N % 128 == 0)
#pragma unroll
            for (int it = 0; it < 2; ++it) {
                int i = tid + it * 256;
                int n  = i >> 2;
                int k4 = (i & 3) * 4;
                float4 v = *(const float4*)(B + (size_t)(col0 + n) * D + kb + k4);
                Bs[k4 + 0][n] = v.x;
                Bs[k4 + 1][n] = v.y;
                Bs[k4 + 2][n] = v.z;
                Bs[k4 + 3][n] = v.w;
            }
            __syncthreads();
            // --- compute: 32 FFMA2 per k-step (64 FMAs) ---
#pragma unroll
            for (int k = 0; k < TK; ++k) {
                u64 b2[4];
#pragma unroll
                for (int j = 0; j < 4; ++j)
                    b2[j] = *(const u64*)&Bs[k][tx * 2 + 32 * j];
#pragma unroll
                for (int i = 0; i < 8; ++i) {
                    u64 a2 = splat2(As[k][ty * 8 + i]);
#pragma unroll
                    for (int j = 0; j < 4; ++j) ffma2(acc[i][j], a2, b2[j]);
                }
            }
            __syncthreads();
        }
    }

    // --- epilogue: bias + optional relu, paired stores ---
#pragma unroll
    for (int i = 0; i < 8; ++i) {
        int row = row0 + ty * 8 + i;
        if (row >= M) continue;
#pragma unroll
        for (int j = 0; j < 4; ++j) {
            int col = col0 + tx * 2 + 32 * j;
            float2 v = unpack2(acc[i][j]);
            v.x += __ldg(bias + col);
            v.y += __ldg(bias + col + 1);
            if (do_relu) { v.x = fmaxf(v.x, 0.f); v.y = fmaxf(v.y, 0.f); }
            *(float2*)(out + (size_t)row * N + col) = v;
        }
    }
}

// ---------------- host launcher ----------------
extern "C" void kernel_launch(void* const* d_in, const int* in_sizes, int n_in,
                              void* d_out, int out_size) {
    const float* x   = (const float*)d_in[0];
    const float* Wl0 = (const float*)d_in[1];
    const float* bl0 = (const float*)d_in[2];
    const float* Wr0 = (const float*)d_in[3];
    const float* Wl1 = (const float*)d_in[4];
    const float* bl1 = (const float*)d_in[5];
    const float* Wr1 = (const float*)d_in[6];
    const int* e0s = (const int*)d_in[7];
    const int* e0d = (const int*)d_in[8];
    const int* e1s = (const int*)d_in[9];
    const int* e1d = (const int*)d_in[10];
    float* out = (float*)d_out;

    void *p_agg0, *p_cnt0, *p_h, *p_agg1, *p_cnt1;
    cudaGetSymbolAddress(&p_agg0, g_agg0);
    cudaGetSymbolAddress(&p_cnt0, g_cnt0);
    cudaGetSymbolAddress(&p_h,    g_h);
    cudaGetSymbolAddress(&p_agg1, g_agg1);
    cudaGetSymbolAddress(&p_cnt1, g_cnt1);

    // 1. zero accumulators
    {
        int blocks = (int)((Z_TOTAL + 255) / 256);
        zero_scratch_kernel<<<blocks, 256>>>();
    }
    // 2. hop-0 scatter
    scatter0_kernel<<<EE0 * 32 / 256, 256>>>((const float4*)x, e0s, e0d);

    // 3. hop-0 dense: h = relu([agg0/cnt | x[:N1]] @ [Wl0|Wr0]^T + b)
    {
        dim3 grid((NN1 + 127) / 128, DH / 128);
        sage_gemm2_kernel<DIN><<<grid, 256>>>(
            (const float*)p_agg0, (const float*)p_cnt0, x,
            Wl0, Wr0, bl0, (float*)p_h, NN1, DH, /*relu=*/1);
    }
    // 4. hop-1 scatter
    scatter1_kernel<<<EE1 * 64 / 256, 256>>>(e1s, e1d);

    // 5. hop-1 dense: out = [agg1/cnt | h[:N2]] @ [Wl1|Wr1]^T + b
    {
        dim3 grid((NN2 + 127) / 128, DOUT / 128);
        sage_gemm2_kernel<DH><<<grid, 256>>>(
            (const float*)p_agg1, (const float*)p_cnt1, (const float*)p_h,
            Wl1, Wr1, bl1, out, NN2, DOUT, /*relu=*/0);
    }
    (void)in_sizes; (void)n_in; (void)out_size;
}

// round 5
// speedup vs baseline: 1.8390x; 1.8390x over previous
#include <cuda_runtime.h>
#include <cstdint>

// Problem sizes (fixed by reference_code)
#define NN0 500000
#define NN1 100000
#define NN2 25000
#define EE0 1600000
#define EE1 400000
#define DIN 128
#define DH  256
#define DOUT 128

// ---------------- device scratch (no allocations allowed) ----------------
__device__ float4 g_agg0[(size_t)NN1 * DIN / 4];   // 51.2 MB
__device__ float4 g_cnt0[NN1 / 4];                 // 0.4 MB
__device__ float4 g_h   [(size_t)NN1 * DH / 4];    // 102.4 MB
__device__ float4 g_agg1[(size_t)NN2 * DH / 4];    // 25.6 MB
__device__ float4 g_cnt1[NN2 / 4];                 // 0.1 MB

// ---------------- zero scratch ----------------
#define Z_AGG0 ((size_t)NN1 * DIN / 4)
#define Z_AGG1 ((size_t)NN2 * DH  / 4)
#define Z_CNT0 ((size_t)NN1 / 4)
#define Z_CNT1 ((size_t)NN2 / 4)
#define Z_TOTAL (Z_AGG0 + Z_AGG1 + Z_CNT0 + Z_CNT1)

__global__ void zero_scratch_kernel() {
    size_t i = (size_t)blockIdx.x * blockDim.x + threadIdx.x;
    if (i >= Z_TOTAL) return;
    const float4 z = make_float4(0.f, 0.f, 0.f, 0.f);
    if (i < Z_AGG0) { g_agg0[i] = z; return; }
    i -= Z_AGG0;
    if (i < Z_AGG1) { g_agg1[i] = z; return; }
    i -= Z_AGG1;
    if (i < Z_CNT0) { g_cnt0[i] = z; return; }
    i -= Z_CNT0;
    g_cnt1[i] = z;
}

// ---------------- edge scatter (atomic mean accumulation) ----------------
__device__ __forceinline__ void red_add_f4(float4* p, float4 v) {
    asm volatile("red.global.add.v4.f32 [%0], {%1,%2,%3,%4};"
                 :: "l"(p), "f"(v.x), "f"(v.y), "f"(v.z), "f"(v.w)
                 : "memory");
}

__global__ void scatter0_kernel(const float4* __restrict__ x4,
                                const int* __restrict__ es,
                                const int* __restrict__ ed) {
    unsigned gtid = blockIdx.x * 256u + threadIdx.x;
    unsigned e = gtid >> 5;
    int lane = gtid & 31;
    int src = es[e];
    int dst = ed[e];
    float4 v = __ldg(&x4[(size_t)src * 32 + lane]);
    red_add_f4(&g_agg0[(size_t)dst * 32 + lane], v);
    if (lane == 0) atomicAdd((float*)g_cnt0 + dst, 1.0f);
}

__global__ void scatter1_kernel(const int* __restrict__ es,
                                const int* __restrict__ ed) {
    unsigned gtid = blockIdx.x * 256u + threadIdx.x;
    unsigned e = gtid >> 6;
    int lane = gtid & 63;
    int src = es[e];
    int dst = ed[e];
    float4 v = g_h[(size_t)src * 64 + lane];
    red_add_f4(&g_agg1[(size_t)dst * 64 + lane], v);
    if (lane == 0) atomicAdd((float*)g_cnt1 + dst, 1.0f);
}

// ---------------- tf32 helpers ----------------
__device__ __forceinline__ uint32_t f2tf32(float f) {
    uint32_t r;
    asm("cvt.rna.tf32.f32 %0, %1;" : "=r"(r) : "f"(f));
    return r;
}
__device__ __forceinline__ void mma_tf32(float* c, const uint32_t* a,
                                         const uint32_t* b) {
    asm volatile(
        "mma.sync.aligned.m16n8k8.row.col.f32.tf32.tf32.f32 "
        "{%0,%1,%2,%3}, {%4,%5,%6,%7}, {%8,%9}, {%0,%1,%2,%3};"
        : "+f"(c[0]), "+f"(c[1]), "+f"(c[2]), "+f"(c[3])
        : "r"(a[0]), "r"(a[1]), "r"(a[2]), "r"(a[3]), "r"(b[0]), "r"(b[1]));
}

// ---------------- fused SAGEConv tf32 mma.sync GEMM ----------------
// out[m,n] = act( sum_k (A0[m,k]/max(cnt[m],1)) * B0[n,k]
//               + sum_k  A1[m,k]                * B1[n,k] + bias[n] )
// A0,A1: [M, KHALF] row-major.  B0,B1: [N, KHALF] row-major.  out: [M, N].
// Block tile 128x128, BK=32, 256 threads = 8 warps (2x4), warp tile 64x32.
// m16n8k8 tf32 fragments loaded from padded SMEM (conflict-free pattern).
template<int KHALF, int N, int DO_RELU>
__global__ __launch_bounds__(256)
void sage_mma_gemm(const float* __restrict__ A0, const float* __restrict__ cnt,
                   const float* __restrict__ A1,
                   const float* __restrict__ B0, const float* __restrict__ B1,
                   const float* __restrict__ bias,
                   float* __restrict__ out, int M) {
    constexpr int BK = 32;
    constexpr int LDS_W = BK + 4;      // pad: (4*row + col) mod 32 all distinct
    __shared__ uint32_t As[128][LDS_W];
    __shared__ uint32_t Bs[128][LDS_W];

    const int tid = threadIdx.x;
    const int wid = tid >> 5;
    const int lane = tid & 31;
    const int lrow = lane >> 2;        // 0..7
    const int lcol = lane & 3;         // 0..3
    const int warp_m = (wid >> 2) * 64;    // 0 or 64
    const int warp_n = (wid & 3) * 32;     // 0,32,64,96
    const int row0 = blockIdx.x * 128;
    const int col0 = blockIdx.y * 128;

    float acc[4][4][4];
#pragma unroll
    for (int mi = 0; mi < 4; ++mi)
#pragma unroll
        for (int ni = 0; ni < 4; ++ni)
#pragma unroll
            for (int j = 0; j < 4; ++j) acc[mi][ni][j] = 0.f;

#pragma unroll 1
    for (int half = 0; half < 2; ++half) {
        const float* __restrict__ A = half ? A1 : A0;
        const float* __restrict__ B = half ? B1 : B0;
#pragma unroll 1
        for (int kb = 0; kb < KHALF; kb += BK) {
            __syncthreads();   // previous compute done before overwrite
            // --- A tile: 128 x 32 = 1024 float4, 4 per thread ---
#pragma unroll
            for (int t = 0; t < 4; ++t) {
                int i = tid + t * 256;
                int r = i >> 3;
                int c4 = (i & 7) * 4;
                int row = row0 + r;
                float4 v = make_float4(0.f, 0.f, 0.f, 0.f);
                float s = 1.0f;
                if (row < M) {
                    v = *(const float4*)(A + (size_t)row * KHALF + kb + c4);
                    if (half == 0) s = 1.0f / fmaxf(__ldg(cnt + row), 1.0f);
                }
                As[r][c4 + 0] = f2tf32(v.x * s);
                As[r][c4 + 1] = f2tf32(v.y * s);
                As[r][c4 + 2] = f2tf32(v.z * s);
                As[r][c4 + 3] = f2tf32(v.w * s);
            }
            // --- B tile: 128 x 32 (col0+n < N always, N % 128 == 0) ---
#pragma unroll
            for (int t = 0; t < 4; ++t) {
                int i = tid + t * 256;
                int n = i >> 3;
                int c4 = (i & 7) * 4;
                float4 v = *(const float4*)(B + (size_t)(col0 + n) * KHALF + kb + c4);
                Bs[n][c4 + 0] = f2tf32(v.x);
                Bs[n][c4 + 1] = f2tf32(v.y);
                Bs[n][c4 + 2] = f2tf32(v.z);
                Bs[n][c4 + 3] = f2tf32(v.w);
            }
            __syncthreads();
            // --- compute: 4 k-steps of m16n8k8 ---
#pragma unroll
            for (int kk = 0; kk < 4; ++kk) {
                const int kof = kk * 8;
                uint32_t af[4][4], bf[4][2];
#pragma unroll
                for (int mi = 0; mi < 4; ++mi) {
                    int m = warp_m + mi * 16 + lrow;
                    af[mi][0] = As[m][kof + lcol];
                    af[mi][1] = As[m + 8][kof + lcol];
                    af[mi][2] = As[m][kof + lcol + 4];
                    af[mi][3] = As[m + 8][kof + lcol + 4];
                }
#pragma unroll
                for (int ni = 0; ni < 4; ++ni) {
                    int n = warp_n + ni * 8 + lrow;
                    bf[ni][0] = Bs[n][kof + lcol];
                    bf[ni][1] = Bs[n][kof + lcol + 4];
                }
#pragma unroll
                for (int mi = 0; mi < 4; ++mi)
#pragma unroll
                    for (int ni = 0; ni < 4; ++ni)
                        mma_tf32(acc[mi][ni], af[mi], bf[ni]);
            }
        }
    }

    // --- epilogue: bias + optional relu, float2 stores ---
#pragma unroll
    for (int mi = 0; mi < 4; ++mi) {
        int r_lo = row0 + warp_m + mi * 16 + lrow;
        int r_hi = r_lo + 8;
#pragma unroll
        for (int ni = 0; ni < 4; ++ni) {
            int c = col0 + warp_n + ni * 8 + 2 * lcol;
            float bx = __ldg(bias + c);
            float by = __ldg(bias + c + 1);
            if (r_lo < M) {
                float2 v = make_float2(acc[mi][ni][0] + bx, acc[mi][ni][1] + by);
                if (DO_RELU) { v.x = fmaxf(v.x, 0.f); v.y = fmaxf(v.y, 0.f); }
                *(float2*)(out + (size_t)r_lo * N + c) = v;
            }
            if (r_hi < M) {
                float2 v = make_float2(acc[mi][ni][2] + bx, acc[mi][ni][3] + by);
                if (DO_RELU) { v.x = fmaxf(v.x, 0.f); v.y = fmaxf(v.y, 0.f); }
                *(float2*)(out + (size_t)r_hi * N + c) = v;
            }
        }
    }
}

// ---------------- host launcher ----------------
extern "C" void kernel_launch(void* const* d_in, const int* in_sizes, int n_in,
                              void* d_out, int out_size) {
    const float* x   = (const float*)d_in[0];
    const float* Wl0 = (const float*)d_in[1];
    const float* bl0 = (const float*)d_in[2];
    const float* Wr0 = (const float*)d_in[3];
    const float* Wl1 = (const float*)d_in[4];
    const float* bl1 = (const float*)d_in[5];
    const float* Wr1 = (const float*)d_in[6];
    const int* e0s = (const int*)d_in[7];
    const int* e0d = (const int*)d_in[8];
    const int* e1s = (const int*)d_in[9];
    const int* e1d = (const int*)d_in[10];
    float* out = (float*)d_out;

    void *p_agg0, *p_cnt0, *p_h, *p_agg1, *p_cnt1;
    cudaGetSymbolAddress(&p_agg0, g_agg0);
    cudaGetSymbolAddress(&p_cnt0, g_cnt0);
    cudaGetSymbolAddress(&p_h,    g_h);
    cudaGetSymbolAddress(&p_agg1, g_agg1);
    cudaGetSymbolAddress(&p_cnt1, g_cnt1);

    // 1. zero accumulators
    zero_scratch_kernel<<<(int)((Z_TOTAL + 255) / 256), 256>>>();

    // 2. hop-0 scatter
    scatter0_kernel<<<EE0 * 32 / 256, 256>>>((const float4*)x, e0s, e0d);

    // 3. hop-0 dense: h = relu([agg0/cnt | x[:N1]] @ [Wl0|Wr0]^T + b)
    {
        dim3 grid((NN1 + 127) / 128, DH / 128);
        sage_mma_gemm<DIN, DH, 1><<<grid, 256>>>(
            (const float*)p_agg0, (const float*)p_cnt0, x,
            Wl0, Wr0, bl0, (float*)p_h, NN1);
    }
    // 4. hop-1 scatter
    scatter1_kernel<<<EE1 * 64 / 256, 256>>>(e1s, e1d);

    // 5. hop-1 dense: out = [agg1/cnt | h[:N2]] @ [Wl1|Wr1]^T + b
    {
        dim3 grid((NN2 + 127) / 128, DOUT / 128);
        sage_mma_gemm<DH, DOUT, 0><<<grid, 256>>>(
            (const float*)p_agg1, (const float*)p_cnt1, (const float*)p_h,
            Wl1, Wr1, bl1, out, NN2);
    }
    (void)in_sizes; (void)n_in; (void)out_size;
}

// round 6
// speedup vs baseline: 3.1413x; 1.7081x over previous
#include <cuda_runtime.h>
#include <cstdint>

// Problem sizes (fixed by reference_code)
#define NN0 500000
#define NN1 100000
#define NN2 25000
#define EE0 1600000
#define EE1 400000
#define DIN 128
#define DH  256
#define DOUT 128
#define MAXDEG 64

// ---------------- device scratch (no allocations allowed) ----------------
__device__ float4 g_agg0[(size_t)NN1 * DIN / 4];   // 51.2 MB (mean, written fully)
__device__ float4 g_h   [(size_t)NN1 * DH / 4];    // 102.4 MB
__device__ float4 g_agg1[(size_t)NN2 * DH / 4];    // 25.6 MB
__device__ int    g_deg0[NN1];
__device__ int    g_deg1[NN2];
__device__ int4   g_srt0[(size_t)NN1 * MAXDEG / 4];  // 25.6 MB, int4 => 16B aligned
__device__ int4   g_srt1[(size_t)NN2 * MAXDEG / 4];  // 6.4 MB

// ---------------- zero degree counters ----------------
__global__ void zero_deg_kernel() {
    int i = blockIdx.x * 256 + threadIdx.x;
    if (i < NN1) g_deg0[i] = 0;
    else if (i < NN1 + NN2) g_deg1[i - NN1] = 0;
}

// ---------------- padded-CSR fill ----------------
__global__ void fill0_kernel(const int* __restrict__ es, const int* __restrict__ ed) {
    int e = blockIdx.x * 256 + threadIdx.x;
    if (e >= EE0) return;
    int dst = ed[e];
    int p = atomicAdd(&g_deg0[dst], 1);
    if (p < MAXDEG) ((int*)g_srt0)[(size_t)dst * MAXDEG + p] = es[e];
}
__global__ void fill1_kernel(const int* __restrict__ es, const int* __restrict__ ed) {
    int e = blockIdx.x * 256 + threadIdx.x;
    if (e >= EE1) return;
    int dst = ed[e];
    int p = atomicAdd(&g_deg1[dst], 1);
    if (p < MAXDEG) ((int*)g_srt1)[(size_t)dst * MAXDEG + p] = es[e];
}

// ---------------- gather-reduce aggregation (mean) ----------------
__device__ __forceinline__ void f4add(float4& a, float4 b) {
    a.x += b.x; a.y += b.y; a.z += b.z; a.w += b.w;
}

// hop 0: D=128 -> one warp per dst, float4 per lane. grid = NN1*32/256 exactly.
__global__ __launch_bounds__(256)
void agg0_kernel(const float4* __restrict__ x4) {
    unsigned gt = blockIdx.x * 256u + threadIdx.x;
    int w = gt >> 5;            // dst node
    int lane = gt & 31;
    int n = min(g_deg0[w], MAXDEG);
    const int4* idx4 = &g_srt0[(size_t)w * (MAXDEG / 4)];
    float4 acc = make_float4(0.f, 0.f, 0.f, 0.f);
    int p = 0;
    for (; p + 4 <= n; p += 4) {
        int4 s = __ldg(idx4 + (p >> 2));   // broadcast across warp
        float4 a = __ldg(&x4[(size_t)s.x * 32 + lane]);
        float4 b = __ldg(&x4[(size_t)s.y * 32 + lane]);
        float4 c = __ldg(&x4[(size_t)s.z * 32 + lane]);
        float4 d = __ldg(&x4[(size_t)s.w * 32 + lane]);
        f4add(acc, a); f4add(acc, b); f4add(acc, c); f4add(acc, d);
    }
    if (p < n) {
        int4 s = __ldg(idx4 + (p >> 2));
        const int rem = n - p;
        f4add(acc, __ldg(&x4[(size_t)s.x * 32 + lane]));
        if (rem > 1) f4add(acc, __ldg(&x4[(size_t)s.y * 32 + lane]));
        if (rem > 2) f4add(acc, __ldg(&x4[(size_t)s.z * 32 + lane]));
    }
    float inv = 1.0f / fmaxf((float)n, 1.0f);
    acc.x *= inv; acc.y *= inv; acc.z *= inv; acc.w *= inv;
    g_agg0[(size_t)w * 32 + lane] = acc;
}

// hop 1: D=256 -> one warp per dst, 2x float4 per lane. grid = NN2*32/256 exactly.
__global__ __launch_bounds__(256)
void agg1_kernel() {
    unsigned gt = blockIdx.x * 256u + threadIdx.x;
    int w = gt >> 5;
    int lane = gt & 31;
    int n = min(g_deg1[w], MAXDEG);
    const int4* idx4 = &g_srt1[(size_t)w * (MAXDEG / 4)];
    float4 acc0 = make_float4(0.f, 0.f, 0.f, 0.f);
    float4 acc1 = make_float4(0.f, 0.f, 0.f, 0.f);
    int p = 0;
    for (; p + 2 <= n; p += 2) {
        int2 s = __ldg((const int2*)idx4 + (p >> 1));
        f4add(acc0, g_h[(size_t)s.x * 64 + lane]);
        f4add(acc1, g_h[(size_t)s.x * 64 + 32 + lane]);
        f4add(acc0, g_h[(size_t)s.y * 64 + lane]);
        f4add(acc1, g_h[(size_t)s.y * 64 + 32 + lane]);
    }
    if (p < n) {
        int s = ((const int*)idx4)[p];
        f4add(acc0, g_h[(size_t)s * 64 + lane]);
        f4add(acc1, g_h[(size_t)s * 64 + 32 + lane]);
    }
    float inv = 1.0f / fmaxf((float)n, 1.0f);
    acc0.x *= inv; acc0.y *= inv; acc0.z *= inv; acc0.w *= inv;
    acc1.x *= inv; acc1.y *= inv; acc1.z *= inv; acc1.w *= inv;
    g_agg1[(size_t)w * 64 + lane] = acc0;
    g_agg1[(size_t)w * 64 + 32 + lane] = acc1;
}

// ---------------- tf32 helpers ----------------
__device__ __forceinline__ uint32_t f2tf32(float f) {
    uint32_t r;
    asm("cvt.rna.tf32.f32 %0, %1;" : "=r"(r) : "f"(f));
    return r;
}
__device__ __forceinline__ void mma_tf32(float* c, const uint32_t* a,
                                         const uint32_t* b) {
    asm volatile(
        "mma.sync.aligned.m16n8k8.row.col.f32.tf32.tf32.f32 "
        "{%0,%1,%2,%3}, {%4,%5,%6,%7}, {%8,%9}, {%0,%1,%2,%3};"
        : "+f"(c[0]), "+f"(c[1]), "+f"(c[2]), "+f"(c[3])
        : "r"(a[0]), "r"(a[1]), "r"(a[2]), "r"(a[3]), "r"(b[0]), "r"(b[1]));
}

// ---------------- fused SAGEConv tf32 mma.sync GEMM ----------------
// out[m,n] = act( sum_k A0[m,k]*B0[n,k] + sum_k A1[m,k]*B1[n,k] + bias[n] )
// (A0 is the precomputed MEAN aggregate; no cnt scaling needed.)
template<int KHALF, int N, int DO_RELU>
__global__ __launch_bounds__(256)
void sage_mma_gemm(const float* __restrict__ A0,
                   const float* __restrict__ A1,
                   const float* __restrict__ B0, const float* __restrict__ B1,
                   const float* __restrict__ bias,
                   float* __restrict__ out, int M) {
    constexpr int BK = 32;
    constexpr int LDS_W = BK + 4;
    __shared__ uint32_t As[128][LDS_W];
    __shared__ uint32_t Bs[128][LDS_W];

    const int tid = threadIdx.x;
    const int wid = tid >> 5;
    const int lane = tid & 31;
    const int lrow = lane >> 2;
    const int lcol = lane & 3;
    const int warp_m = (wid >> 2) * 64;
    const int warp_n = (wid & 3) * 32;
    const int row0 = blockIdx.x * 128;
    const int col0 = blockIdx.y * 128;

    float acc[4][4][4];
#pragma unroll
    for (int mi = 0; mi < 4; ++mi)
#pragma unroll
        for (int ni = 0; ni < 4; ++ni)
#pragma unroll
            for (int j = 0; j < 4; ++j) acc[mi][ni][j] = 0.f;

#pragma unroll 1
    for (int half = 0; half < 2; ++half) {
        const float* __restrict__ A = half ? A1 : A0;
        const float* __restrict__ B = half ? B1 : B0;
#pragma unroll 1
        for (int kb = 0; kb < KHALF; kb += BK) {
            __syncthreads();
#pragma unroll
            for (int t = 0; t < 4; ++t) {
                int i = tid + t * 256;
                int r = i >> 3;
                int c4 = (i & 7) * 4;
                int row = row0 + r;
                float4 v = make_float4(0.f, 0.f, 0.f, 0.f);
                if (row < M)
                    v = *(const float4*)(A + (size_t)row * KHALF + kb + c4);
                As[r][c4 + 0] = f2tf32(v.x);
                As[r][c4 + 1] = f2tf32(v.y);
                As[r][c4 + 2] = f2tf32(v.z);
                As[r][c4 + 3] = f2tf32(v.w);
            }
#pragma unroll
            for (int t = 0; t < 4; ++t) {
                int i = tid + t * 256;
                int n = i >> 3;
                int c4 = (i & 7) * 4;
                float4 v = *(const float4*)(B + (size_t)(col0 + n) * KHALF + kb + c4);
                Bs[n][c4 + 0] = f2tf32(v.x);
                Bs[n][c4 + 1] = f2tf32(v.y);
                Bs[n][c4 + 2] = f2tf32(v.z);
                Bs[n][c4 + 3] = f2tf32(v.w);
            }
            __syncthreads();
#pragma unroll
            for (int kk = 0; kk < 4; ++kk) {
                const int kof = kk * 8;
                uint32_t af[4][4], bf[4][2];
#pragma unroll
                for (int mi = 0; mi < 4; ++mi) {
                    int m = warp_m + mi * 16 + lrow;
                    af[mi][0] = As[m][kof + lcol];
                    af[mi][1] = As[m + 8][kof + lcol];
                    af[mi][2] = As[m][kof + lcol + 4];
                    af[mi][3] = As[m + 8][kof + lcol + 4];
                }
#pragma unroll
                for (int ni = 0; ni < 4; ++ni) {
                    int n = warp_n + ni * 8 + lrow;
                    bf[ni][0] = Bs[n][kof + lcol];
                    bf[ni][1] = Bs[n][kof + lcol + 4];
                }
#pragma unroll
                for (int mi = 0; mi < 4; ++mi)
#pragma unroll
                    for (int ni = 0; ni < 4; ++ni)
                        mma_tf32(acc[mi][ni], af[mi], bf[ni]);
            }
        }
    }

#pragma unroll
    for (int mi = 0; mi < 4; ++mi) {
        int r_lo = row0 + warp_m + mi * 16 + lrow;
        int r_hi = r_lo + 8;
#pragma unroll
        for (int ni = 0; ni < 4; ++ni) {
            int c = col0 + warp_n + ni * 8 + 2 * lcol;
            float bx = __ldg(bias + c);
            float by = __ldg(bias + c + 1);
            if (r_lo < M) {
                float2 v = make_float2(acc[mi][ni][0] + bx, acc[mi][ni][1] + by);
                if (DO_RELU) { v.x = fmaxf(v.x, 0.f); v.y = fmaxf(v.y, 0.f); }
                *(float2*)(out + (size_t)r_lo * N + c) = v;
            }
            if (r_hi < M) {
                float2 v = make_float2(acc[mi][ni][2] + bx, acc[mi][ni][3] + by);
                if (DO_RELU) { v.x = fmaxf(v.x, 0.f); v.y = fmaxf(v.y, 0.f); }
                *(float2*)(out + (size_t)r_hi * N + c) = v;
            }
        }
    }
}

// ---------------- host launcher ----------------
extern "C" void kernel_launch(void* const* d_in, const int* in_sizes, int n_in,
                              void* d_out, int out_size) {
    const float* x   = (const float*)d_in[0];
    const float* Wl0 = (const float*)d_in[1];
    const float* bl0 = (const float*)d_in[2];
    const float* Wr0 = (const float*)d_in[3];
    const float* Wl1 = (const float*)d_in[4];
    const float* bl1 = (const float*)d_in[5];
    const float* Wr1 = (const float*)d_in[6];
    const int* e0s = (const int*)d_in[7];
    const int* e0d = (const int*)d_in[8];
    const int* e1s = (const int*)d_in[9];
    const int* e1d = (const int*)d_in[10];
    float* out = (float*)d_out;

    void *p_agg0, *p_h, *p_agg1;
    cudaGetSymbolAddress(&p_agg0, g_agg0);
    cudaGetSymbolAddress(&p_h,    g_h);
    cudaGetSymbolAddress(&p_agg1, g_agg1);

    // 1. zero degree counters
    zero_deg_kernel<<<(NN1 + NN2 + 255) / 256, 256>>>();

    // 2. build padded CSR for both hops (independent of compute)
    fill0_kernel<<<(EE0 + 255) / 256, 256>>>(e0s, e0d);
    fill1_kernel<<<(EE1 + 255) / 256, 256>>>(e1s, e1d);

    // 3. hop-0 aggregate (mean)
    agg0_kernel<<<NN1 * 32 / 256, 256>>>((const float4*)x);

    // 4. hop-0 dense: h = relu([agg0 | x[:N1]] @ [Wl0|Wr0]^T + b)
    {
        dim3 grid((NN1 + 127) / 128, DH / 128);
        sage_mma_gemm<DIN, DH, 1><<<grid, 256>>>(
            (const float*)p_agg0, x, Wl0, Wr0, bl0, (float*)p_h, NN1);
    }

    // 5. hop-1 aggregate (mean)
    agg1_kernel<<<NN2 * 32 / 256, 256>>>();

    // 6. hop-1 dense: out = [agg1 | h[:N2]] @ [Wl1|Wr1]^T + b
    {
        dim3 grid((NN2 + 127) / 128, DOUT / 128);
        sage_mma_gemm<DH, DOUT, 0><<<grid, 256>>>(
            (const float*)p_agg1, (const float*)p_h, Wl1, Wr1, bl1, out, NN2);
    }
    (void)in_sizes; (void)n_in; (void)out_size;
}

// round 7
// speedup vs baseline: 3.1458x; 1.0014x over previous
#include <cuda_runtime.h>
#include <cstdint>

// Problem sizes (fixed by reference_code)
#define NN0 500000
#define NN1 100000
#define NN2 25000
#define EE0 1600000
#define EE1 400000
#define DIN 128
#define DH  256
#define DOUT 128
#define MAXDEG 64
#define SPLIT0 250000   // x-table L2 working-set split point

// ---------------- device scratch (no allocations allowed) ----------------
__device__ float4 g_agg0[(size_t)NN1 * DIN / 4];   // 51.2 MB
__device__ float4 g_h   [(size_t)NN1 * DH / 4];    // 102.4 MB
__device__ float4 g_agg1[(size_t)NN2 * DH / 4];    // 25.6 MB
__device__ int    g_deg0[NN1];
__device__ int    g_deg1[NN2];
__device__ int4   g_srt0[(size_t)NN1 * MAXDEG / 4];  // 25.6 MB
__device__ int4   g_srt1[(size_t)NN2 * MAXDEG / 4];  // 6.4 MB

// ---------------- zero degree counters ----------------
__global__ void zero_deg_kernel() {
    int i = blockIdx.x * 256 + threadIdx.x;
    if (i < NN1) g_deg0[i] = 0;
    else if (i < NN1 + NN2) g_deg1[i - NN1] = 0;
}

// ---------------- padded-CSR fill ----------------
__global__ void fill0_kernel(const int* __restrict__ es, const int* __restrict__ ed) {
    int e = blockIdx.x * 256 + threadIdx.x;
    if (e >= EE0) return;
    int dst = ed[e];
    int p = atomicAdd(&g_deg0[dst], 1);
    if (p < MAXDEG) ((int*)g_srt0)[(size_t)dst * MAXDEG + p] = es[e];
}
__global__ void fill1_kernel(const int* __restrict__ es, const int* __restrict__ ed) {
    int e = blockIdx.x * 256 + threadIdx.x;
    if (e >= EE1) return;
    int dst = ed[e];
    int p = atomicAdd(&g_deg1[dst], 1);
    if (p < MAXDEG) ((int*)g_srt1)[(size_t)dst * MAXDEG + p] = es[e];
}

// ---------------- gather-reduce aggregation (mean) ----------------
__device__ __forceinline__ void f4add(float4& a, float4 b) {
    a.x += b.x; a.y += b.y; a.z += b.z; a.w += b.w;
}

// hop 0, two passes over src ranges so each pass's gather set ~fits L2.
// LO=1: src in [0, SPLIT0), writes raw partial sums.
// LO=0: src in [SPLIT0, NN0), adds partials, finalizes mean.
template<int LO>
__global__ __launch_bounds__(256)
void agg0_pass_kernel(const float4* __restrict__ x4) {
    unsigned gt = blockIdx.x * 256u + threadIdx.x;
    int w = gt >> 5;            // dst node (grid sized exactly NN1*32/256)
    int lane = gt & 31;
    int n = min(g_deg0[w], MAXDEG);
    const int4* idx4 = &g_srt0[(size_t)w * (MAXDEG / 4)];
    float4 acc = make_float4(0.f, 0.f, 0.f, 0.f);
    for (int p = 0; p < n; p += 4) {
        int4 s = __ldg(idx4 + (p >> 2));   // warp-uniform broadcast
        if ((LO ? (s.x < SPLIT0) : (s.x >= SPLIT0)))
            f4add(acc, __ldg(&x4[(size_t)s.x * 32 + lane]));
        if (p + 1 < n && (LO ? (s.y < SPLIT0) : (s.y >= SPLIT0)))
            f4add(acc, __ldg(&x4[(size_t)s.y * 32 + lane]));
        if (p + 2 < n && (LO ? (s.z < SPLIT0) : (s.z >= SPLIT0)))
            f4add(acc, __ldg(&x4[(size_t)s.z * 32 + lane]));
        if (p + 3 < n && (LO ? (s.w < SPLIT0) : (s.w >= SPLIT0)))
            f4add(acc, __ldg(&x4[(size_t)s.w * 32 + lane]));
    }
    if (LO) {
        g_agg0[(size_t)w * 32 + lane] = acc;           // raw partial
    } else {
        f4add(acc, g_agg0[(size_t)w * 32 + lane]);     // + low-half partial
        float inv = 1.0f / fmaxf((float)n, 1.0f);
        acc.x *= inv; acc.y *= inv; acc.z *= inv; acc.w *= inv;
        g_agg0[(size_t)w * 32 + lane] = acc;           // mean
    }
}

// hop 1: D=256 -> one warp per dst, 2x float4 per lane (h ~L2-resident).
__global__ __launch_bounds__(256)
void agg1_kernel() {
    unsigned gt = blockIdx.x * 256u + threadIdx.x;
    int w = gt >> 5;
    int lane = gt & 31;
    int n = min(g_deg1[w], MAXDEG);
    const int4* idx4 = &g_srt1[(size_t)w * (MAXDEG / 4)];
    float4 acc0 = make_float4(0.f, 0.f, 0.f, 0.f);
    float4 acc1 = make_float4(0.f, 0.f, 0.f, 0.f);
    int p = 0;
    for (; p + 2 <= n; p += 2) {
        int2 s = __ldg((const int2*)idx4 + (p >> 1));
        f4add(acc0, g_h[(size_t)s.x * 64 + lane]);
        f4add(acc1, g_h[(size_t)s.x * 64 + 32 + lane]);
        f4add(acc0, g_h[(size_t)s.y * 64 + lane]);
        f4add(acc1, g_h[(size_t)s.y * 64 + 32 + lane]);
    }
    if (p < n) {
        int s = ((const int*)idx4)[p];
        f4add(acc0, g_h[(size_t)s * 64 + lane]);
        f4add(acc1, g_h[(size_t)s * 64 + 32 + lane]);
    }
    float inv = 1.0f / fmaxf((float)n, 1.0f);
    acc0.x *= inv; acc0.y *= inv; acc0.z *= inv; acc0.w *= inv;
    acc1.x *= inv; acc1.y *= inv; acc1.z *= inv; acc1.w *= inv;
    g_agg1[(size_t)w * 64 + lane] = acc0;
    g_agg1[(size_t)w * 64 + 32 + lane] = acc1;
}

// ---------------- tf32 helpers ----------------
__device__ __forceinline__ uint32_t f2tf32(float f) {
    uint32_t r;
    asm("cvt.rna.tf32.f32 %0, %1;" : "=r"(r) : "f"(f));
    return r;
}
__device__ __forceinline__ void mma_tf32(float* c, const uint32_t* a,
                                         const uint32_t* b) {
    asm volatile(
        "mma.sync.aligned.m16n8k8.row.col.f32.tf32.tf32.f32 "
        "{%0,%1,%2,%3}, {%4,%5,%6,%7}, {%8,%9}, {%0,%1,%2,%3};"
        : "+f"(c[0]), "+f"(c[1]), "+f"(c[2]), "+f"(c[3])
        : "r"(a[0]), "r"(a[1]), "r"(a[2]), "r"(a[3]), "r"(b[0]), "r"(b[1]));
}

// ---------------- fused SAGEConv tf32 mma.sync GEMM (pipelined) ----------------
// out[m,n] = act( sum_k A0[m,k]*B0[n,k] + sum_k A1[m,k]*B1[n,k] + bias[n] )
// Block tile 128x128, BK=32, 256 threads, warp tile 64x32 (m16n8k8).
// Double-buffered dynamic SMEM + register prefetch of next chunk's LDGs;
// one __syncthreads per chunk.
template<int KHALF, int N, int DO_RELU>
__global__ __launch_bounds__(256)
void sage_mma_gemm(const float* __restrict__ A0,
                   const float* __restrict__ A1,
                   const float* __restrict__ B0, const float* __restrict__ B1,
                   const float* __restrict__ bias,
                   float* __restrict__ out, int M) {
    constexpr int BK = 32;
    constexpr int LDS_W = BK + 4;      // conflict-free fragment pattern
    constexpr int CH = KHALF / BK;
    constexpr int NC = 2 * CH;

    extern __shared__ uint32_t sm[];
    // As[2][128][LDS_W], Bs[2][128][LDS_W]
    uint32_t (*As)[128][LDS_W] = (uint32_t (*)[128][LDS_W])sm;
    uint32_t (*Bs)[128][LDS_W] = (uint32_t (*)[128][LDS_W])(sm + 2 * 128 * LDS_W);

    const int tid = threadIdx.x;
    const int wid = tid >> 5;
    const int lane = tid & 31;
    const int lrow = lane >> 2;
    const int lcol = lane & 3;
    const int warp_m = (wid >> 2) * 64;
    const int warp_n = (wid & 3) * 32;
    const int row0 = blockIdx.x * 128;
    const int col0 = blockIdx.y * 128;

    float acc[4][4][4];
#pragma unroll
    for (int mi = 0; mi < 4; ++mi)
#pragma unroll
        for (int ni = 0; ni < 4; ++ni)
#pragma unroll
            for (int j = 0; j < 4; ++j) acc[mi][ni][j] = 0.f;

    float4 pa[4], pb[4];

    auto ldg_chunk = [&](int c) {
        const float* __restrict__ A = (c < CH) ? A0 : A1;
        const float* __restrict__ B = (c < CH) ? B0 : B1;
        const int kb = ((c < CH) ? c : c - CH) * BK;
#pragma unroll
        for (int t = 0; t < 4; ++t) {
            int i = tid + t * 256;
            int r = i >> 3;
            int c4 = (i & 7) * 4;
            int row = row0 + r;
            pa[t] = make_float4(0.f, 0.f, 0.f, 0.f);
            if (row < M)
                pa[t] = *(const float4*)(A + (size_t)row * KHALF + kb + c4);
            pb[t] = *(const float4*)(B + (size_t)(col0 + r) * KHALF + kb + c4);
        }
    };
    auto sts_chunk = [&](int buf) {
#pragma unroll
        for (int t = 0; t < 4; ++t) {
            int i = tid + t * 256;
            int r = i >> 3;
            int c4 = (i & 7) * 4;
            As[buf][r][c4 + 0] = f2tf32(pa[t].x);
            As[buf][r][c4 + 1] = f2tf32(pa[t].y);
            As[buf][r][c4 + 2] = f2tf32(pa[t].z);
            As[buf][r][c4 + 3] = f2tf32(pa[t].w);
            Bs[buf][r][c4 + 0] = f2tf32(pb[t].x);
            Bs[buf][r][c4 + 1] = f2tf32(pb[t].y);
            Bs[buf][r][c4 + 2] = f2tf32(pb[t].z);
            Bs[buf][r][c4 + 3] = f2tf32(pb[t].w);
        }
    };

    // prologue
    ldg_chunk(0);
    sts_chunk(0);
    __syncthreads();

#pragma unroll 1
    for (int c = 0; c < NC; ++c) {
        const int buf = c & 1;
        const bool more = (c + 1 < NC);
        if (more) ldg_chunk(c + 1);          // overlap with compute below
        // --- compute current chunk: 4 k-steps of m16n8k8 ---
#pragma unroll
        for (int kk = 0; kk < 4; ++kk) {
            const int kof = kk * 8;
            uint32_t af[4][4], bf[4][2];
#pragma unroll
            for (int mi = 0; mi < 4; ++mi) {
                int m = warp_m + mi * 16 + lrow;
                af[mi][0] = As[buf][m][kof + lcol];
                af[mi][1] = As[buf][m + 8][kof + lcol];
                af[mi][2] = As[buf][m][kof + lcol + 4];
                af[mi][3] = As[buf][m + 8][kof + lcol + 4];
            }
#pragma unroll
            for (int ni = 0; ni < 4; ++ni) {
                int n = warp_n + ni * 8 + lrow;
                bf[ni][0] = Bs[buf][n][kof + lcol];
                bf[ni][1] = Bs[buf][n][kof + lcol + 4];
            }
#pragma unroll
            for (int mi = 0; mi < 4; ++mi)
#pragma unroll
                for (int ni = 0; ni < 4; ++ni)
                    mma_tf32(acc[mi][ni], af[mi], bf[ni]);
        }
        if (more) {
            sts_chunk(buf ^ 1);   // safe: buf^1 last read in iter c-1, pre-sync
            __syncthreads();
        }
    }

    // --- epilogue: bias + optional relu ---
#pragma unroll
    for (int mi = 0; mi < 4; ++mi) {
        int r_lo = row0 + warp_m + mi * 16 + lrow;
        int r_hi = r_lo + 8;
#pragma unroll
        for (int ni = 0; ni < 4; ++ni) {
            int c = col0 + warp_n + ni * 8 + 2 * lcol;
            float bx = __ldg(bias + c);
            float by = __ldg(bias + c + 1);
            if (r_lo < M) {
                float2 v = make_float2(acc[mi][ni][0] + bx, acc[mi][ni][1] + by);
                if (DO_RELU) { v.x = fmaxf(v.x, 0.f); v.y = fmaxf(v.y, 0.f); }
                *(float2*)(out + (size_t)r_lo * N + c) = v;
            }
            if (r_hi < M) {
                float2 v = make_float2(acc[mi][ni][2] + bx, acc[mi][ni][3] + by);
                if (DO_RELU) { v.x = fmaxf(v.x, 0.f); v.y = fmaxf(v.y, 0.f); }
                *(float2*)(out + (size_t)r_hi * N + c) = v;
            }
        }
    }
}

#define GEMM_SMEM (4 * 128 * 36 * 4)   // 73728 bytes

// ---------------- host launcher ----------------
extern "C" void kernel_launch(void* const* d_in, const int* in_sizes, int n_in,
                              void* d_out, int out_size) {
    const float* x   = (const float*)d_in[0];
    const float* Wl0 = (const float*)d_in[1];
    const float* bl0 = (const float*)d_in[2];
    const float* Wr0 = (const float*)d_in[3];
    const float* Wl1 = (const float*)d_in[4];
    const float* bl1 = (const float*)d_in[5];
    const float* Wr1 = (const float*)d_in[6];
    const int* e0s = (const int*)d_in[7];
    const int* e0d = (const int*)d_in[8];
    const int* e1s = (const int*)d_in[9];
    const int* e1d = (const int*)d_in[10];
    float* out = (float*)d_out;

    void *p_agg0, *p_h, *p_agg1;
    cudaGetSymbolAddress(&p_agg0, g_agg0);
    cudaGetSymbolAddress(&p_h,    g_h);
    cudaGetSymbolAddress(&p_agg1, g_agg1);

    cudaFuncSetAttribute(sage_mma_gemm<DIN, DH, 1>,
                         cudaFuncAttributeMaxDynamicSharedMemorySize, GEMM_SMEM);
    cudaFuncSetAttribute(sage_mma_gemm<DH, DOUT, 0>,
                         cudaFuncAttributeMaxDynamicSharedMemorySize, GEMM_SMEM);

    // 1. zero degree counters
    zero_deg_kernel<<<(NN1 + NN2 + 255) / 256, 256>>>();

    // 2. build padded CSR for both hops
    fill0_kernel<<<(EE0 + 255) / 256, 256>>>(e0s, e0d);
    fill1_kernel<<<(EE1 + 255) / 256, 256>>>(e1s, e1d);

    // 3. hop-0 aggregate (mean), split by src range for L2 residency
    agg0_pass_kernel<1><<<NN1 * 32 / 256, 256>>>((const float4*)x);
    agg0_pass_kernel<0><<<NN1 * 32 / 256, 256>>>((const float4*)x);

    // 4. hop-0 dense: h = relu([agg0 | x[:N1]] @ [Wl0|Wr0]^T + b)
    {
        dim3 grid((NN1 + 127) / 128, DH / 128);
        sage_mma_gemm<DIN, DH, 1><<<grid, 256, GEMM_SMEM>>>(
            (const float*)p_agg0, x, Wl0, Wr0, bl0, (float*)p_h, NN1);
    }

    // 5. hop-1 aggregate (mean)
    agg1_kernel<<<NN2 * 32 / 256, 256>>>();

    // 6. hop-1 dense: out = [agg1 | h[:N2]] @ [Wl1|Wr1]^T + b
    {
        dim3 grid((NN2 + 127) / 128, DOUT / 128);
        sage_mma_gemm<DH, DOUT, 0><<<grid, 256, GEMM_SMEM>>>(
            (const float*)p_agg1, (const float*)p_h, Wl1, Wr1, bl1, out, NN2);
    }
    (void)in_sizes; (void)n_in; (void)out_size;
}